// round 2
// baseline (speedup 1.0000x reference)
#include <cuda_runtime.h>
#include <math_constants.h>

#define NQ 8
#define KCB 2048
#define DIM 512
#define BB 32
#define TT 1500
#define QELEMS (BB*DIM*TT)      /* 24576000 */
#define TM 128
#define TN 128
#define KB 16
#define TILES_PER_B 12          /* ceil(1500/128) */

__device__ float  g_residual[QELEMS];
__device__ float  g_cbT[NQ*DIM*KCB];
__device__ float  g_cnorm[NQ*KCB];
__device__ double g_loss;

__global__ void init_kernel() { g_loss = 0.0; }

// cbT[q][d][k] = cb[q][k][d], tiled 32x32 transpose
__global__ void transpose_kernel(const float* __restrict__ cb) {
    __shared__ float tile[32][33];
    int q  = blockIdx.z;
    int k0 = blockIdx.x * 32;
    int d0 = blockIdx.y * 32;
    const float* src = cb + (size_t)q * KCB * DIM;
    float* dst = g_cbT + (size_t)q * DIM * KCB;
    int tx = threadIdx.x, ty = threadIdx.y;
    #pragma unroll
    for (int i = 0; i < 32; i += 8)
        tile[ty + i][tx] = src[(size_t)(k0 + ty + i) * DIM + d0 + tx];
    __syncthreads();
    #pragma unroll
    for (int i = 0; i < 32; i += 8)
        dst[(size_t)(d0 + ty + i) * KCB + k0 + tx] = tile[tx][ty + i];
}

// one warp per codeword row: cnorm[row] = sum_d cb[row][d]^2
__global__ void cnorm_kernel(const float* __restrict__ cb) {
    int row  = blockIdx.x * 8 + (threadIdx.x >> 5);
    int lane = threadIdx.x & 31;
    const float* p = cb + (size_t)row * DIM;
    float s = 0.f;
    for (int i = lane; i < DIM; i += 32) {
        float v = p[i];
        s = __fadd_rn(s, __fmul_rn(v, v));
    }
    #pragma unroll
    for (int off = 16; off; off >>= 1) s += __shfl_down_sync(0xffffffffu, s, off);
    if (lane == 0) g_cnorm[row] = s;
}

// Fused VQ stage: GEMM scores + argmin + straight-through residual update + loss
__global__ __launch_bounds__(256, 2) void vq_stage_kernel(
    const float* __restrict__ x, const float* __restrict__ cb_all,
    float* qacc, float* idx_out, int stage)
{
    const float* src = (stage == 0) ? x : (const float*)g_residual;
    const float* cb  = cb_all + (size_t)stage * KCB * DIM;   // row-major [K][D]
    const float* cbT = g_cbT  + (size_t)stage * DIM * KCB;   // [D][K]
    const float* cn  = g_cnorm + stage * KCB;

    int bb  = blockIdx.x / TILES_PER_B;
    int t0  = (blockIdx.x % TILES_PER_B) * TM;
    int tmv = min(TM, TT - t0);
    const float* srcb = src + (size_t)bb * DIM * TT;

    __shared__ float As[KB][TM];
    __shared__ float Bs[KB][TN];
    __shared__ float xnorm_s[TM];
    __shared__ float best_s[TM];
    __shared__ int   bidx_s[TM];
    __shared__ float wsum_s[8];

    int tid = threadIdx.x;

    // per-row ||x||^2 (sequential d, products rounded then summed like ref)
    if (tid < TM) {
        float s = 0.f;
        if (tid < tmv) {
            const float* p = srcb + t0 + tid;
            for (int d = 0; d < DIM; d++) {
                float v = p[(size_t)d * TT];
                s = __fadd_rn(s, __fmul_rn(v, v));
            }
        }
        xnorm_s[tid] = s;
        best_s[tid]  = CUDART_INF_F;
        bidx_s[tid]  = 0;
    }
    __syncthreads();

    int ty = tid >> 4, tx = tid & 15;          // 16x16 thread grid, 8x8 micro-tile
    int lr = tid & 127, ks = tid >> 7;         // loader mapping

    for (int j0 = 0; j0 < KCB; j0 += TN) {
        float acc[8][8];
        #pragma unroll
        for (int ri = 0; ri < 8; ri++)
            #pragma unroll
            for (int ci = 0; ci < 8; ci++) acc[ri][ci] = 0.f;

        for (int k0 = 0; k0 < DIM; k0 += KB) {
            #pragma unroll
            for (int i = 0; i < 8; i++) {
                int kk = ks + i * 2;
                float av = 0.f;
                if (lr < tmv) av = srcb[(size_t)(k0 + kk) * TT + t0 + lr];
                As[kk][lr] = av;
                Bs[kk][lr] = cbT[(size_t)(k0 + kk) * KCB + j0 + lr];
            }
            __syncthreads();
            #pragma unroll
            for (int kk = 0; kk < KB; kk++) {
                float a[8], bv[8];
                *(float4*)&a[0]  = *(const float4*)&As[kk][ty * 8];
                *(float4*)&a[4]  = *(const float4*)&As[kk][ty * 8 + 4];
                *(float4*)&bv[0] = *(const float4*)&Bs[kk][tx * 8];
                *(float4*)&bv[4] = *(const float4*)&Bs[kk][tx * 8 + 4];
                #pragma unroll
                for (int ri = 0; ri < 8; ri++)
                    #pragma unroll
                    for (int ci = 0; ci < 8; ci++)
                        acc[ri][ci] += a[ri] * bv[ci];
            }
            __syncthreads();
        }

        // fold this 128-column tile into the running argmin
        #pragma unroll
        for (int ri = 0; ri < 8; ri++) {
            int row = ty * 8 + ri;
            float xn = xnorm_s[row];
            float bvv = CUDART_INF_F; int bi = 0x7fffffff;
            #pragma unroll
            for (int ci = 0; ci < 8; ci++) {
                int col = j0 + tx * 8 + ci;
                float s1 = __fadd_rn(xn, -2.0f * acc[ri][ci]);   // (A - B)
                float s2 = __fadd_rn(s1, cn[col]);               // + C
                if (s2 < bvv) { bvv = s2; bi = col; }            // first-index tie-break
            }
            #pragma unroll
            for (int off = 8; off; off >>= 1) {
                float ov = __shfl_down_sync(0xffffffffu, bvv, off, 16);
                int   oi = __shfl_down_sync(0xffffffffu, bi,  off, 16);
                if (ov < bvv || (ov == bvv && oi < bi)) { bvv = ov; bi = oi; }
            }
            if (tx == 0 && bvv < best_s[row]) { best_s[row] = bvv; bidx_s[row] = bi; }
        }
        __syncthreads();
    }

    // indices (cast to float — single-dtype output buffer)
    if (tid < tmv)
        idx_out[(size_t)bb * (NQ * TT) + stage * TT + t0 + tid] = (float)bidx_s[tid];

    // straight-through update, exact ref rounding:
    // t1 = quant - r; q_out = r + t1; qacc += q_out; r' = r - q_out; loss += t1^2
    float lsum = 0.f;
    {
        int r = tid & 127, dg = tid >> 7;
        if (r < tmv) {
            const float* crow = cb + (size_t)bidx_s[r] * DIM;
            size_t base = (size_t)bb * DIM * TT + t0 + r;
            for (int d = dg; d < DIM; d += 2) {
                size_t gi = base + (size_t)d * TT;
                float old   = src[gi];
                float quant = crow[d];
                float t1   = __fadd_rn(quant, -old);
                float qout = __fadd_rn(old, t1);
                if (stage == 0) qacc[gi] = qout;
                else            qacc[gi] = __fadd_rn(qacc[gi], qout);
                g_residual[gi] = __fadd_rn(old, -qout);
                lsum = __fadd_rn(lsum, __fmul_rn(t1, t1));
            }
        }
    }
    #pragma unroll
    for (int off = 16; off; off >>= 1) lsum += __shfl_down_sync(0xffffffffu, lsum, off);
    if ((tid & 31) == 0) wsum_s[tid >> 5] = lsum;
    __syncthreads();
    if (tid == 0) {
        float s = 0.f;
        #pragma unroll
        for (int i = 0; i < 8; i++) s += wsum_s[i];
        atomicAdd(&g_loss, (double)s);
    }
}

__global__ void finalize_kernel(float* out_loss) {
    *out_loss = (float)(g_loss / (double)QELEMS);
}

extern "C" void kernel_launch(void* const* d_in, const int* in_sizes, int n_in,
                              void* d_out, int out_size) {
    const float* x  = (const float*)d_in[0];
    const float* cb = (const float*)d_in[1];
    float* out      = (float*)d_out;
    float* qacc     = out;                 // [32,512,1500]
    float* idx_out  = out + QELEMS;        // [32,8,1500]
    float* loss_out = out + (out_size - 1);

    init_kernel<<<1, 1>>>();
    transpose_kernel<<<dim3(KCB / 32, DIM / 32, NQ), dim3(32, 8)>>>(cb);
    cnorm_kernel<<<(NQ * KCB) / 8, 256>>>(cb);
    for (int q = 0; q < NQ; q++)
        vq_stage_kernel<<<BB * TILES_PER_B, 256>>>(x, cb, qacc, idx_out, q);
    finalize_kernel<<<1, 1>>>(loss_out);
}